// round 1
// baseline (speedup 1.0000x reference)
#include <cuda_runtime.h>

#define NV 50000
#define NE 10000
#define NM 200000
#define DD 512
#define BN_EPS 1e-5f

// ---------------- scratch (static device globals; no allocation) ----------------
__device__ float g_Y[(size_t)NV * DD];          // GEMM output (pre-BN), 102.4 MB
__device__ float g_HE_scratch[(size_t)NE * DD]; // fallback if HE not in d_out
__device__ float g_stats[2 * DD];               // [0:512) colsum, [512:1024) colsumsq
__device__ float g_scale[DD];
__device__ float g_shift[DD];
__device__ int   g_deg_e[NE];
__device__ int   g_deg_v[NV];

// ---------------- zeroing ----------------
__global__ void k_zero(float* p, long n) {
    long stride = (long)gridDim.x * blockDim.x;
    for (long i = (long)blockIdx.x * blockDim.x + threadIdx.x; i < n; i += stride)
        p[i] = 0.0f;
}

__global__ void k_zero_misc() {
    int i = blockIdx.x * blockDim.x + threadIdx.x;
    if (i < 2 * DD) g_stats[i] = 0.0f;
    if (i < NE)     g_deg_e[i] = 0;
    if (i < NV)     g_deg_v[i] = 0;
}

// ---------------- degree counting ----------------
__global__ void k_deg(const int* __restrict__ v_idx, const int* __restrict__ e_idx) {
    int i = blockIdx.x * blockDim.x + threadIdx.x;
    if (i < NM) {
        atomicAdd(&g_deg_v[v_idx[i]], 1);
        atomicAdd(&g_deg_e[e_idx[i]], 1);
    }
}

// ---------------- SGEMM: g_Y = X[NV,512] @ W[512,512] + b ----------------
// 128x128 block tile, BK=8, 256 threads, 8x8 per thread in 2x2 quadrants.
__global__ __launch_bounds__(256) void k_gemm(const float* __restrict__ A,
                                              const float* __restrict__ B,
                                              const float* __restrict__ bias) {
    __shared__ float As[8][128];
    __shared__ float Bs[8][128];

    const int tid  = threadIdx.x;
    const int tx   = tid & 15;       // 0..15
    const int ty   = tid >> 4;       // 0..15
    const int row0 = blockIdx.y * 128;
    const int col0 = blockIdx.x * 128;

    // A load: thread -> one float4; row = tid>>1 (0..127), kcol = (tid&1)*4
    const int arow = tid >> 1;
    const int acol = (tid & 1) * 4;
    // B load: row k = tid>>5 (0..7), col = (tid&31)*4
    const int brow = tid >> 5;
    const int bcol = (tid & 31) * 4;

    float acc[8][8];
#pragma unroll
    for (int i = 0; i < 8; i++)
#pragma unroll
        for (int j = 0; j < 8; j++) acc[i][j] = 0.0f;

    for (int k0 = 0; k0 < DD; k0 += 8) {
        int gr = row0 + arow;
        float4 av = make_float4(0.f, 0.f, 0.f, 0.f);
        if (gr < NV) av = *(const float4*)(A + (size_t)gr * DD + k0 + acol);
        As[acol + 0][arow] = av.x;
        As[acol + 1][arow] = av.y;
        As[acol + 2][arow] = av.z;
        As[acol + 3][arow] = av.w;

        float4 bv = *(const float4*)(B + (size_t)(k0 + brow) * DD + col0 + bcol);
        *(float4*)&Bs[brow][bcol] = bv;
        __syncthreads();

#pragma unroll
        for (int k = 0; k < 8; k++) {
            float4 a0 = *(const float4*)&As[k][ty * 4];
            float4 a1 = *(const float4*)&As[k][64 + ty * 4];
            float4 b0 = *(const float4*)&Bs[k][tx * 4];
            float4 b1 = *(const float4*)&Bs[k][64 + tx * 4];
            float a[8] = {a0.x, a0.y, a0.z, a0.w, a1.x, a1.y, a1.z, a1.w};
            float b[8] = {b0.x, b0.y, b0.z, b0.w, b1.x, b1.y, b1.z, b1.w};
#pragma unroll
            for (int i = 0; i < 8; i++)
#pragma unroll
                for (int j = 0; j < 8; j++) acc[i][j] = fmaf(a[i], b[j], acc[i][j]);
        }
        __syncthreads();
    }

    // epilogue: add bias, store
#pragma unroll
    for (int rg = 0; rg < 2; rg++) {
#pragma unroll
        for (int i = 0; i < 4; i++) {
            int r = row0 + rg * 64 + ty * 4 + i;
            if (r < NV) {
#pragma unroll
                for (int cg = 0; cg < 2; cg++) {
                    int c = col0 + cg * 64 + tx * 4;
                    float4 bb = *(const float4*)(bias + c);
                    float4 o;
                    o.x = acc[rg * 4 + i][cg * 4 + 0] + bb.x;
                    o.y = acc[rg * 4 + i][cg * 4 + 1] + bb.y;
                    o.z = acc[rg * 4 + i][cg * 4 + 2] + bb.z;
                    o.w = acc[rg * 4 + i][cg * 4 + 3] + bb.w;
                    *(float4*)(g_Y + (size_t)r * DD + c) = o;
                }
            }
        }
    }
}

// ---------------- per-column BN stats over g_Y ----------------
__global__ void k_colstats() {
    int c = threadIdx.x;  // 512 threads = one per column
    float s = 0.0f, s2 = 0.0f;
    for (int r = blockIdx.x; r < NV; r += gridDim.x) {
        float v = g_Y[(size_t)r * DD + c];
        s += v;
        s2 += v * v;
    }
    atomicAdd(&g_stats[c], s);
    atomicAdd(&g_stats[DD + c], s2);
}

__global__ void k_finalize(const float* __restrict__ gamma, const float* __restrict__ beta) {
    int c = threadIdx.x;  // 512
    float mu  = g_stats[c] * (1.0f / NV);
    float var = g_stats[DD + c] * (1.0f / NV) - mu * mu;
    float rs  = rsqrtf(var + BN_EPS);
    float sc  = gamma[c] * rs;
    g_scale[c] = sc;
    g_shift[c] = beta[c] - mu * sc;
}

// ---------------- v2e: HE[e] += BN(Y[v]) / deg_e[e] ----------------
// work item = (incidence m, float4 chunk). 128 chunks of 4 cols per incidence.
__global__ void k_v2e(const int* __restrict__ v_idx, const int* __restrict__ e_idx,
                      float* __restrict__ HE) {
    long idx = (long)blockIdx.x * blockDim.x + threadIdx.x;
    if (idx >= (long)NM * 128) return;
    int m  = (int)(idx >> 7);
    int c4 = ((int)idx & 127) * 4;
    int v = v_idx[m];
    int e = e_idx[m];
    float w = 1.0f / (float)g_deg_e[e];
    float4 y  = *(const float4*)(g_Y + (size_t)v * DD + c4);
    float4 sc = *(const float4*)(g_scale + c4);
    float4 sh = *(const float4*)(g_shift + c4);
    float* he = HE + (size_t)e * DD + c4;
    atomicAdd(he + 0, (fmaf(y.x, sc.x, sh.x)) * w);
    atomicAdd(he + 1, (fmaf(y.y, sc.y, sh.y)) * w);
    atomicAdd(he + 2, (fmaf(y.z, sc.z, sh.z)) * w);
    atomicAdd(he + 3, (fmaf(y.w, sc.w, sh.w)) * w);
}

// ---------------- e2v: X_out[v] += HE[e] / deg_v[v] ----------------
__global__ void k_e2v(const int* __restrict__ v_idx, const int* __restrict__ e_idx,
                      const float* __restrict__ HE, float* __restrict__ Xout) {
    long idx = (long)blockIdx.x * blockDim.x + threadIdx.x;
    if (idx >= (long)NM * 128) return;
    int m  = (int)(idx >> 7);
    int c4 = ((int)idx & 127) * 4;
    int v = v_idx[m];
    int e = e_idx[m];
    float w = 1.0f / (float)g_deg_v[v];
    float4 h = *(const float4*)(HE + (size_t)e * DD + c4);
    float* xo = Xout + (size_t)v * DD + c4;
    atomicAdd(xo + 0, h.x * w);
    atomicAdd(xo + 1, h.y * w);
    atomicAdd(xo + 2, h.z * w);
    atomicAdd(xo + 3, h.w * w);
}

// ---------------- launcher ----------------
extern "C" void kernel_launch(void* const* d_in, const int* in_sizes, int n_in,
                              void* d_out, int out_size) {
    const float* X     = (const float*)d_in[0];
    const float* W     = (const float*)d_in[1];
    const float* b     = (const float*)d_in[2];
    const float* gamma = (const float*)d_in[3];
    const float* beta  = (const float*)d_in[4];
    const int* v_idx   = (const int*)d_in[5];
    const int* e_idx   = (const int*)d_in[6];

    float* Xout = (float*)d_out;
    float* HE;
    bool he_in_out = ((long)out_size >= (long)(NV + NE) * DD);
    if (he_in_out) {
        HE = Xout + (size_t)NV * DD;
    } else {
        void* p = nullptr;
        cudaGetSymbolAddress(&p, g_HE_scratch);
        HE = (float*)p;
    }

    // zero outputs (poisoned by harness) + HE region + misc
    k_zero<<<2048, 256>>>((float*)d_out, (long)out_size);
    if (!he_in_out) k_zero<<<512, 256>>>(HE, (long)NE * DD);
    k_zero_misc<<<(NV + 255) / 256, 256>>>();

    // degrees
    k_deg<<<(NM + 255) / 256, 256>>>(v_idx, e_idx);

    // GEMM  Y = X @ W + b
    dim3 gg(DD / 128, (NV + 127) / 128);
    k_gemm<<<gg, 256>>>(X, W, b);

    // BN stats + fold into scale/shift
    k_colstats<<<256, DD>>>();
    k_finalize<<<1, DD>>>(gamma, beta);

    // scatter passes
    long work = (long)NM * 128;
    int blocks = (int)((work + 255) / 256);
    k_v2e<<<blocks, 256>>>(v_idx, e_idx, HE);
    k_e2v<<<blocks, 256>>>(v_idx, e_idx, HE, Xout);
}

// round 3
// speedup vs baseline: 1.8017x; 1.8017x over previous
#include <cuda_runtime.h>

#define NV 50000
#define NE 10000
#define NM 200000
#define DD 512
#define BN_EPS 1e-5f

// ---------------- scratch (static device globals; no allocation) ----------------
__device__ float g_Y[(size_t)NV * DD];   // GEMM output (pre-BN), 102.4 MB
__device__ float g_stats[2 * DD];        // [0:512) colsum, [512:1024) colsumsq
__device__ float g_scale[DD];
__device__ float g_shift[DD];
__device__ int   g_deg_e[NE];
__device__ int   g_deg_v[NV];
__device__ int   g_cur_e[NE];
__device__ int   g_cur_v[NV];
__device__ int   g_off_e[NE + 1];
__device__ int   g_off_v[NV + 1];
__device__ int   g_csr_e_v[NM];          // per edge slot: vertex id
__device__ int   g_csr_v_e[NM];          // per vertex slot: edge id

// ---------------- zeroing ----------------
__global__ void k_zero(float* p, long n) {
    long stride = (long)gridDim.x * blockDim.x;
    for (long i = (long)blockIdx.x * blockDim.x + threadIdx.x; i < n; i += stride)
        p[i] = 0.0f;
}

__global__ void k_zero_misc() {
    int i = blockIdx.x * blockDim.x + threadIdx.x;
    if (i < 2 * DD) g_stats[i] = 0.0f;
    if (i < NE) { g_deg_e[i] = 0; g_cur_e[i] = 0; }
    if (i < NV) { g_deg_v[i] = 0; g_cur_v[i] = 0; }
}

// ---------------- degree counting ----------------
__global__ void k_deg(const int* __restrict__ v_idx, const int* __restrict__ e_idx) {
    int i = blockIdx.x * blockDim.x + threadIdx.x;
    if (i < NM) {
        atomicAdd(&g_deg_v[v_idx[i]], 1);
        atomicAdd(&g_deg_e[e_idx[i]], 1);
    }
}

// ---------------- exclusive scan (single block; globals referenced in device code) ----
// mode 0: scan g_deg_e[NE] -> g_off_e ; mode 1: scan g_deg_v[NV] -> g_off_v
__global__ void k_scan(int mode) {
    const int* __restrict__ deg = (mode == 0) ? g_deg_e : g_deg_v;
    int* __restrict__ off       = (mode == 0) ? g_off_e : g_off_v;
    const int n                 = (mode == 0) ? NE : NV;

    __shared__ int s[1024];
    int carry = 0;
    for (int base = 0; base < n; base += 1024) {
        int i = base + threadIdx.x;
        int v = (i < n) ? deg[i] : 0;
        s[threadIdx.x] = v;
        __syncthreads();
        for (int d = 1; d < 1024; d <<= 1) {
            int t = (threadIdx.x >= d) ? s[threadIdx.x - d] : 0;
            __syncthreads();
            s[threadIdx.x] += t;
            __syncthreads();
        }
        if (i < n) off[i] = carry + s[threadIdx.x] - v;
        carry += s[1023];
        __syncthreads();
    }
    if (threadIdx.x == 0) off[n] = carry;
}

// ---------------- CSR fill (int atomics only) ----------------
__global__ void k_fill(const int* __restrict__ v_idx, const int* __restrict__ e_idx) {
    int i = blockIdx.x * blockDim.x + threadIdx.x;
    if (i < NM) {
        int v = v_idx[i];
        int e = e_idx[i];
        int pe = atomicAdd(&g_cur_e[e], 1);
        g_csr_e_v[g_off_e[e] + pe] = v;
        int pv = atomicAdd(&g_cur_v[v], 1);
        g_csr_v_e[g_off_v[v] + pv] = e;
    }
}

// ---------------- SGEMM: g_Y = X[NV,512] @ W[512,512] + b ----------------
__global__ __launch_bounds__(256) void k_gemm(const float* __restrict__ A,
                                              const float* __restrict__ B,
                                              const float* __restrict__ bias) {
    __shared__ float As[8][128];
    __shared__ float Bs[8][128];

    const int tid  = threadIdx.x;
    const int tx   = tid & 15;
    const int ty   = tid >> 4;
    const int row0 = blockIdx.y * 128;
    const int col0 = blockIdx.x * 128;

    const int arow = tid >> 1;
    const int acol = (tid & 1) * 4;
    const int brow = tid >> 5;
    const int bcol = (tid & 31) * 4;

    float acc[8][8];
#pragma unroll
    for (int i = 0; i < 8; i++)
#pragma unroll
        for (int j = 0; j < 8; j++) acc[i][j] = 0.0f;

    for (int k0 = 0; k0 < DD; k0 += 8) {
        int gr = row0 + arow;
        float4 av = make_float4(0.f, 0.f, 0.f, 0.f);
        if (gr < NV) av = *(const float4*)(A + (size_t)gr * DD + k0 + acol);
        As[acol + 0][arow] = av.x;
        As[acol + 1][arow] = av.y;
        As[acol + 2][arow] = av.z;
        As[acol + 3][arow] = av.w;

        float4 bv = *(const float4*)(B + (size_t)(k0 + brow) * DD + col0 + bcol);
        *(float4*)&Bs[brow][bcol] = bv;
        __syncthreads();

#pragma unroll
        for (int k = 0; k < 8; k++) {
            float4 a0 = *(const float4*)&As[k][ty * 4];
            float4 a1 = *(const float4*)&As[k][64 + ty * 4];
            float4 b0 = *(const float4*)&Bs[k][tx * 4];
            float4 b1 = *(const float4*)&Bs[k][64 + tx * 4];
            float a[8] = {a0.x, a0.y, a0.z, a0.w, a1.x, a1.y, a1.z, a1.w};
            float b[8] = {b0.x, b0.y, b0.z, b0.w, b1.x, b1.y, b1.z, b1.w};
#pragma unroll
            for (int i = 0; i < 8; i++)
#pragma unroll
                for (int j = 0; j < 8; j++) acc[i][j] = fmaf(a[i], b[j], acc[i][j]);
        }
        __syncthreads();
    }

#pragma unroll
    for (int rg = 0; rg < 2; rg++) {
#pragma unroll
        for (int i = 0; i < 4; i++) {
            int r = row0 + rg * 64 + ty * 4 + i;
            if (r < NV) {
#pragma unroll
                for (int cg = 0; cg < 2; cg++) {
                    int c = col0 + cg * 64 + tx * 4;
                    float4 bb = *(const float4*)(bias + c);
                    float4 o;
                    o.x = acc[rg * 4 + i][cg * 4 + 0] + bb.x;
                    o.y = acc[rg * 4 + i][cg * 4 + 1] + bb.y;
                    o.z = acc[rg * 4 + i][cg * 4 + 2] + bb.z;
                    o.w = acc[rg * 4 + i][cg * 4 + 3] + bb.w;
                    *(float4*)(g_Y + (size_t)r * DD + c) = o;
                }
            }
        }
    }
}

// ---------------- per-column BN stats over g_Y ----------------
__global__ void k_colstats() {
    int c = threadIdx.x;  // 512 threads = one per column
    float s = 0.0f, s2 = 0.0f;
    for (int r = blockIdx.x; r < NV; r += gridDim.x) {
        float v = g_Y[(size_t)r * DD + c];
        s += v;
        s2 += v * v;
    }
    atomicAdd(&g_stats[c], s);
    atomicAdd(&g_stats[DD + c], s2);
}

__global__ void k_finalize(const float* __restrict__ gamma, const float* __restrict__ beta) {
    int c = threadIdx.x;  // 512
    float mu  = g_stats[c] * (1.0f / NV);
    float var = g_stats[DD + c] * (1.0f / NV) - mu * mu;
    float rs  = rsqrtf(var + BN_EPS);
    float sc  = gamma[c] * rs;
    g_scale[c] = sc;
    g_shift[c] = beta[c] - mu * sc;
}

// ---------------- v2e (CSR gather): HE[e] = scale * mean_v(Y[v]) + shift ----------------
__global__ __launch_bounds__(128) void k_v2e(float* __restrict__ HE) {
    int e  = blockIdx.x;
    int c4 = threadIdx.x * 4;
    int s = g_off_e[e], t = g_off_e[e + 1];
    float4 acc = make_float4(0.f, 0.f, 0.f, 0.f);
    int j = s;
    for (; j + 4 <= t; j += 4) {
        int v0 = g_csr_e_v[j + 0];
        int v1 = g_csr_e_v[j + 1];
        int v2 = g_csr_e_v[j + 2];
        int v3 = g_csr_e_v[j + 3];
        float4 y0 = *(const float4*)(g_Y + (size_t)v0 * DD + c4);
        float4 y1 = *(const float4*)(g_Y + (size_t)v1 * DD + c4);
        float4 y2 = *(const float4*)(g_Y + (size_t)v2 * DD + c4);
        float4 y3 = *(const float4*)(g_Y + (size_t)v3 * DD + c4);
        acc.x += (y0.x + y1.x) + (y2.x + y3.x);
        acc.y += (y0.y + y1.y) + (y2.y + y3.y);
        acc.z += (y0.z + y1.z) + (y2.z + y3.z);
        acc.w += (y0.w + y1.w) + (y2.w + y3.w);
    }
    for (; j < t; j++) {
        int v = g_csr_e_v[j];
        float4 y = *(const float4*)(g_Y + (size_t)v * DD + c4);
        acc.x += y.x; acc.y += y.y; acc.z += y.z; acc.w += y.w;
    }
    float w = 1.0f / (float)max(t - s, 1);
    float4 sc = *(const float4*)(g_scale + c4);
    float4 sh = *(const float4*)(g_shift + c4);
    float4 o;
    o.x = fmaf(acc.x * w, sc.x, sh.x);
    o.y = fmaf(acc.y * w, sc.y, sh.y);
    o.z = fmaf(acc.z * w, sc.z, sh.z);
    o.w = fmaf(acc.w * w, sc.w, sh.w);
    *(float4*)(HE + (size_t)e * DD + c4) = o;
}

// ---------------- e2v (CSR gather): X_out[v] = mean_e(HE[e]) ----------------
__global__ __launch_bounds__(128) void k_e2v(const float* __restrict__ HE,
                                             float* __restrict__ Xout) {
    int v  = blockIdx.x;
    int c4 = threadIdx.x * 4;
    int s = g_off_v[v], t = g_off_v[v + 1];
    float4 acc = make_float4(0.f, 0.f, 0.f, 0.f);
    int j = s;
    for (; j + 4 <= t; j += 4) {
        int e0 = g_csr_v_e[j + 0];
        int e1 = g_csr_v_e[j + 1];
        int e2 = g_csr_v_e[j + 2];
        int e3 = g_csr_v_e[j + 3];
        float4 h0 = *(const float4*)(HE + (size_t)e0 * DD + c4);
        float4 h1 = *(const float4*)(HE + (size_t)e1 * DD + c4);
        float4 h2 = *(const float4*)(HE + (size_t)e2 * DD + c4);
        float4 h3 = *(const float4*)(HE + (size_t)e3 * DD + c4);
        acc.x += (h0.x + h1.x) + (h2.x + h3.x);
        acc.y += (h0.y + h1.y) + (h2.y + h3.y);
        acc.z += (h0.z + h1.z) + (h2.z + h3.z);
        acc.w += (h0.w + h1.w) + (h2.w + h3.w);
    }
    for (; j < t; j++) {
        int e = g_csr_v_e[j];
        float4 h = *(const float4*)(HE + (size_t)e * DD + c4);
        acc.x += h.x; acc.y += h.y; acc.z += h.z; acc.w += h.w;
    }
    float w = 1.0f / (float)max(t - s, 1);
    float4 o = make_float4(acc.x * w, acc.y * w, acc.z * w, acc.w * w);
    *(float4*)(Xout + (size_t)v * DD + c4) = o;
}

// ---------------- launcher ----------------
extern "C" void kernel_launch(void* const* d_in, const int* in_sizes, int n_in,
                              void* d_out, int out_size) {
    const float* X     = (const float*)d_in[0];
    const float* W     = (const float*)d_in[1];
    const float* b     = (const float*)d_in[2];
    const float* gamma = (const float*)d_in[3];
    const float* beta  = (const float*)d_in[4];
    const int* v_idx   = (const int*)d_in[5];
    const int* e_idx   = (const int*)d_in[6];

    float* Xout = (float*)d_out;
    float* HE   = Xout + (size_t)NV * DD;  // validated by Round-1 pass

    // zero small scratch (stats, degrees, cursors)
    k_zero_misc<<<(NV + 255) / 256, 256>>>();

    // zero any tail of d_out beyond the region we fully write
    long expected = (long)(NV + NE) * DD;
    if ((long)out_size > expected)
        k_zero<<<64, 256>>>(Xout + expected, (long)out_size - expected);

    // CSR build (globals referenced inside kernels; no symbol passing from host)
    k_deg<<<(NM + 255) / 256, 256>>>(v_idx, e_idx);
    k_scan<<<1, 1024>>>(0);   // edges
    k_scan<<<1, 1024>>>(1);   // vertices
    k_fill<<<(NM + 255) / 256, 256>>>(v_idx, e_idx);

    // GEMM  Y = X @ W + b
    dim3 gg(DD / 128, (NV + 127) / 128);
    k_gemm<<<gg, 256>>>(X, W, b);

    // BN stats folded into per-column scale/shift
    k_colstats<<<256, DD>>>();
    k_finalize<<<1, DD>>>(gamma, beta);

    // gather-based segment means (no float atomics)
    k_v2e<<<NE, 128>>>(HE);
    k_e2v<<<NV, 128>>>(HE, Xout);
}

// round 5
// speedup vs baseline: 2.5486x; 1.4146x over previous
#include <cuda_runtime.h>
#include <cuda_bf16.h>
#include <cstdint>

#define NV 50000
#define NE 10000
#define NM 200000
#define DD 512
#define BN_EPS 1e-5f

// ---------------- scratch (static device globals; no allocation) ----------------
__device__ float g_Y[(size_t)NV * DD];            // GEMM output (pre-BN)
__device__ __nv_bfloat16 g_Xh[(size_t)NV * DD];   // hi bf16 split of X
__device__ __nv_bfloat16 g_Xl[(size_t)NV * DD];   // lo bf16 split of X
__device__ __nv_bfloat16 g_Wth[DD * DD];          // W^T hi split  [n][k]
__device__ __nv_bfloat16 g_Wtl[DD * DD];          // W^T lo split  [n][k]
__device__ float g_stats[2 * DD];
__device__ float g_scale[DD];
__device__ float g_shift[DD];
__device__ int   g_deg_e[NE];
__device__ int   g_deg_v[NV];
__device__ int   g_cur_e[NE];
__device__ int   g_cur_v[NV];
__device__ int   g_off_e[NE + 1];
__device__ int   g_off_v[NV + 1];
__device__ int   g_csr_e_v[NM];
__device__ int   g_csr_v_e[NM];

// ---------------- helpers ----------------
__device__ __forceinline__ uint32_t smem_u32(const void* p) {
    uint32_t a;
    asm("{ .reg .u64 t; cvta.to.shared.u64 t, %1; cvt.u32.u64 %0, t; }" : "=r"(a) : "l"(p));
    return a;
}
__device__ __forceinline__ void ldm_x4(uint32_t* r, uint32_t addr) {
    asm volatile("ldmatrix.sync.aligned.m8n8.x4.shared.b16 {%0,%1,%2,%3}, [%4];"
                 : "=r"(r[0]), "=r"(r[1]), "=r"(r[2]), "=r"(r[3]) : "r"(addr));
}
__device__ __forceinline__ void mma16816(float* d, const uint32_t* a, const uint32_t* b) {
    asm volatile(
        "mma.sync.aligned.m16n8k16.row.col.f32.bf16.bf16.f32 "
        "{%0,%1,%2,%3}, {%4,%5,%6,%7}, {%8,%9}, {%0,%1,%2,%3};"
        : "+f"(d[0]), "+f"(d[1]), "+f"(d[2]), "+f"(d[3])
        : "r"(a[0]), "r"(a[1]), "r"(a[2]), "r"(a[3]), "r"(b[0]), "r"(b[1]));
}

// ---------------- zeroing ----------------
__global__ void k_zero(float* p, long n) {
    long stride = (long)gridDim.x * blockDim.x;
    for (long i = (long)blockIdx.x * blockDim.x + threadIdx.x; i < n; i += stride)
        p[i] = 0.0f;
}
__global__ void k_zero_misc() {
    int i = blockIdx.x * blockDim.x + threadIdx.x;
    if (i < 2 * DD) g_stats[i] = 0.0f;
    if (i < NE) { g_deg_e[i] = 0; g_cur_e[i] = 0; }
    if (i < NV) { g_deg_v[i] = 0; g_cur_v[i] = 0; }
}

// ---------------- degree counting ----------------
__global__ void k_deg(const int* __restrict__ v_idx, const int* __restrict__ e_idx) {
    int i = blockIdx.x * blockDim.x + threadIdx.x;
    if (i < NM) {
        atomicAdd(&g_deg_v[v_idx[i]], 1);
        atomicAdd(&g_deg_e[e_idx[i]], 1);
    }
}

// ---------------- fast exclusive scan (single block, 1024 thr, shfl) ----------------
__global__ void k_scan(int mode) {
    const int* __restrict__ deg = (mode == 0) ? g_deg_e : g_deg_v;
    int* __restrict__ off       = (mode == 0) ? g_off_e : g_off_v;
    const int n                 = (mode == 0) ? NE : NV;

    const int tid  = threadIdx.x;
    const int lane = tid & 31;
    const int w    = tid >> 5;
    const int per  = (n + 1023) >> 10;
    const int start = tid * per;
    const int end   = min(start + per, n);

    int local = 0;
    for (int i = start; i < end; i++) local += deg[i];

    int v = local;
#pragma unroll
    for (int d = 1; d < 32; d <<= 1) {
        int t = __shfl_up_sync(0xFFFFFFFFu, v, d);
        if (lane >= d) v += t;
    }
    __shared__ int wsum[32];
    if (lane == 31) wsum[w] = v;
    __syncthreads();
    if (w == 0) {
        int x = wsum[lane];
#pragma unroll
        for (int d = 1; d < 32; d <<= 1) {
            int t = __shfl_up_sync(0xFFFFFFFFu, x, d);
            if (lane >= d) x += t;
        }
        wsum[lane] = x;
    }
    __syncthreads();
    int excl = v - local + ((w > 0) ? wsum[w - 1] : 0);

    int run = excl;
    for (int i = start; i < end; i++) { off[i] = run; run += deg[i]; }
    if (end == n) off[n] = run;
}

// ---------------- CSR fill ----------------
__global__ void k_fill(const int* __restrict__ v_idx, const int* __restrict__ e_idx) {
    int i = blockIdx.x * blockDim.x + threadIdx.x;
    if (i < NM) {
        int v = v_idx[i];
        int e = e_idx[i];
        int pe = atomicAdd(&g_cur_e[e], 1);
        g_csr_e_v[g_off_e[e] + pe] = v;
        int pv = atomicAdd(&g_cur_v[v], 1);
        g_csr_v_e[g_off_v[v] + pv] = e;
    }
}

// ---------------- split X into bf16 hi/lo ----------------
__global__ void k_splitX(const float* __restrict__ X) {
    long n4 = (long)NV * DD / 4;
    long stride = (long)gridDim.x * blockDim.x;
    for (long i4 = (long)blockIdx.x * blockDim.x + threadIdx.x; i4 < n4; i4 += stride) {
        float4 v = ((const float4*)X)[i4];
        __nv_bfloat16 h0 = __float2bfloat16(v.x);
        __nv_bfloat16 h1 = __float2bfloat16(v.y);
        __nv_bfloat16 h2 = __float2bfloat16(v.z);
        __nv_bfloat16 h3 = __float2bfloat16(v.w);
        __nv_bfloat16 l0 = __float2bfloat16(v.x - __bfloat162float(h0));
        __nv_bfloat16 l1 = __float2bfloat16(v.y - __bfloat162float(h1));
        __nv_bfloat16 l2 = __float2bfloat16(v.z - __bfloat162float(h2));
        __nv_bfloat16 l3 = __float2bfloat16(v.w - __bfloat162float(h3));
        __nv_bfloat162 hh01; hh01.x = h0; hh01.y = h1;
        __nv_bfloat162 hh23; hh23.x = h2; hh23.y = h3;
        __nv_bfloat162 ll01; ll01.x = l0; ll01.y = l1;
        __nv_bfloat162 ll23; ll23.x = l2; ll23.y = l3;
        ((__nv_bfloat162*)g_Xh)[i4 * 2 + 0] = hh01;
        ((__nv_bfloat162*)g_Xh)[i4 * 2 + 1] = hh23;
        ((__nv_bfloat162*)g_Xl)[i4 * 2 + 0] = ll01;
        ((__nv_bfloat162*)g_Xl)[i4 * 2 + 1] = ll23;
    }
}

// ---------------- split + transpose W ----------------
__global__ void k_splitW(const float* __restrict__ W) {
    int i = blockIdx.x * blockDim.x + threadIdx.x;  // i = n*512 + k
    if (i < DD * DD) {
        int n = i >> 9, k = i & 511;
        float v = W[(size_t)k * DD + n];
        __nv_bfloat16 h = __float2bfloat16(v);
        __nv_bfloat16 l = __float2bfloat16(v - __bfloat162float(h));
        g_Wth[i] = h;
        g_Wtl[i] = l;
    }
}

// ---------------- mma.sync GEMM: g_Y = X @ W + b via split-bf16 ----------------
// Block 128x128, BK=32. 8 warps: warp_m(0..1)*64 x warp_n(0..3)*32 tiles.
// smem rows padded to 40 bf16 (80B) -> ldmatrix conflict-free.
#define SPAD 40
__global__ __launch_bounds__(256, 2) void k_gemm_mma(const float* __restrict__ bias) {
    __shared__ __align__(16) __nv_bfloat16 As[128 * SPAD];
    __shared__ __align__(16) __nv_bfloat16 Bs[128 * SPAD];

    const int tid    = threadIdx.x;
    const int wid    = tid >> 5;
    const int lane   = tid & 31;
    const int warp_m = wid >> 2;   // 0..1
    const int warp_n = wid & 3;    // 0..3
    const int row0   = blockIdx.y * 128;
    const int n0     = blockIdx.x * 128;

    const uint32_t as_base = smem_u32(As);
    const uint32_t bs_base = smem_u32(Bs);

    // ldmatrix lane addressing (element offsets; x2 bytes at use)
    // A x4: lanes 0-7 rows m..m+7 @k, 8-15 rows m+8..15 @k, 16-23 rows m..7 @k+8, 24-31 rows m+8..15 @k+8
    const int a_row = warp_m * 64 + (lane & 15);
    const int a_col = ((lane >> 4) << 3);
    // B x4 (non-trans, Wt [n][k]): lanes 0-7 n..n+7 @k, 8-15 n..n+7 @k+8, 16-23 n+8..15 @k, 24-31 n+8..15 @k+8
    const int b_row = warp_n * 32 + ((lane >> 4) << 3) + (lane & 7);
    const int b_col = ((lane >> 3) & 1) << 3;

    float acc[4][4][4];
#pragma unroll
    for (int i = 0; i < 4; i++)
#pragma unroll
        for (int j = 0; j < 4; j++)
#pragma unroll
            for (int r = 0; r < 4; r++) acc[i][j][r] = 0.0f;

#pragma unroll 1
    for (int seg = 0; seg < 3; seg++) {
        const __nv_bfloat16* Ap = (seg < 2) ? g_Xh : g_Xl;
        const __nv_bfloat16* Bp = (seg == 1) ? g_Wtl : g_Wth;

#pragma unroll 1
        for (int kt = 0; kt < DD / 32; kt++) {
            const int k0 = kt * 32;
            // load 128x32 A and B tiles (each thread: 2 uint4 per tile)
#pragma unroll
            for (int i = 0; i < 2; i++) {
                int idx = tid + i * 256;       // 0..511
                int r = idx >> 2;              // 0..127
                int q = (idx & 3) * 8;         // bf16 col
                int gr = row0 + r;
                uint4 va = make_uint4(0, 0, 0, 0);
                if (gr < NV) va = *(const uint4*)(Ap + (size_t)gr * DD + k0 + q);
                *(uint4*)(As + r * SPAD + q) = va;
                uint4 vb = *(const uint4*)(Bp + (size_t)(n0 + r) * DD + k0 + q);
                *(uint4*)(Bs + r * SPAD + q) = vb;
            }
            __syncthreads();

#pragma unroll
            for (int k16 = 0; k16 < 2; k16++) {
                const int kk = k16 * 16;
                uint32_t a[4][4];
#pragma unroll
                for (int mt = 0; mt < 4; mt++)
                    ldm_x4(a[mt], as_base + ((a_row + mt * 16) * SPAD + a_col + kk) * 2);
                uint32_t bfr[2][4];
#pragma unroll
                for (int np = 0; np < 2; np++)
                    ldm_x4(bfr[np], bs_base + ((b_row + np * 16) * SPAD + b_col + kk) * 2);
#pragma unroll
                for (int mt = 0; mt < 4; mt++)
#pragma unroll
                    for (int nt = 0; nt < 4; nt++)
                        mma16816(acc[mt][nt], a[mt], &bfr[nt >> 1][(nt & 1) * 2]);
            }
            __syncthreads();
        }
    }

    // epilogue: D frag -> g_Y (+bias)
    const int mrow = lane >> 2;
    const int mcol = (lane & 3) * 2;
#pragma unroll
    for (int mt = 0; mt < 4; mt++) {
#pragma unroll
        for (int nt = 0; nt < 4; nt++) {
            int gc = n0 + warp_n * 32 + nt * 8 + mcol;
            float2 bb = *(const float2*)(bias + gc);
            int gr0 = row0 + warp_m * 64 + mt * 16 + mrow;
            if (gr0 < NV) {
                float2 o = make_float2(acc[mt][nt][0] + bb.x, acc[mt][nt][1] + bb.y);
                *(float2*)(g_Y + (size_t)gr0 * DD + gc) = o;
            }
            int gr1 = gr0 + 8;
            if (gr1 < NV) {
                float2 o = make_float2(acc[mt][nt][2] + bb.x, acc[mt][nt][3] + bb.y);
                *(float2*)(g_Y + (size_t)gr1 * DD + gc) = o;
            }
        }
    }
}

// ---------------- per-column BN stats over g_Y ----------------
__global__ void k_colstats() {
    int c = threadIdx.x;
    float s = 0.0f, s2 = 0.0f;
    for (int r = blockIdx.x; r < NV; r += gridDim.x) {
        float v = g_Y[(size_t)r * DD + c];
        s += v;
        s2 += v * v;
    }
    atomicAdd(&g_stats[c], s);
    atomicAdd(&g_stats[DD + c], s2);
}

__global__ void k_finalize(const float* __restrict__ gamma, const float* __restrict__ beta) {
    int c = threadIdx.x;
    float mu  = g_stats[c] * (1.0f / NV);
    float var = g_stats[DD + c] * (1.0f / NV) - mu * mu;
    float rs  = rsqrtf(var + BN_EPS);
    float sc  = gamma[c] * rs;
    g_scale[c] = sc;
    g_shift[c] = beta[c] - mu * sc;
}

// ---------------- v2e (CSR gather) ----------------
__global__ __launch_bounds__(128) void k_v2e(float* __restrict__ HE) {
    int e  = blockIdx.x;
    int c4 = threadIdx.x * 4;
    int s = g_off_e[e], t = g_off_e[e + 1];
    float4 acc = make_float4(0.f, 0.f, 0.f, 0.f);
    int j = s;
    for (; j + 4 <= t; j += 4) {
        int v0 = g_csr_e_v[j + 0];
        int v1 = g_csr_e_v[j + 1];
        int v2 = g_csr_e_v[j + 2];
        int v3 = g_csr_e_v[j + 3];
        float4 y0 = *(const float4*)(g_Y + (size_t)v0 * DD + c4);
        float4 y1 = *(const float4*)(g_Y + (size_t)v1 * DD + c4);
        float4 y2 = *(const float4*)(g_Y + (size_t)v2 * DD + c4);
        float4 y3 = *(const float4*)(g_Y + (size_t)v3 * DD + c4);
        acc.x += (y0.x + y1.x) + (y2.x + y3.x);
        acc.y += (y0.y + y1.y) + (y2.y + y3.y);
        acc.z += (y0.z + y1.z) + (y2.z + y3.z);
        acc.w += (y0.w + y1.w) + (y2.w + y3.w);
    }
    for (; j < t; j++) {
        int v = g_csr_e_v[j];
        float4 y = *(const float4*)(g_Y + (size_t)v * DD + c4);
        acc.x += y.x; acc.y += y.y; acc.z += y.z; acc.w += y.w;
    }
    float w = 1.0f / (float)max(t - s, 1);
    float4 sc = *(const float4*)(g_scale + c4);
    float4 sh = *(const float4*)(g_shift + c4);
    float4 o;
    o.x = fmaf(acc.x * w, sc.x, sh.x);
    o.y = fmaf(acc.y * w, sc.y, sh.y);
    o.z = fmaf(acc.z * w, sc.z, sh.z);
    o.w = fmaf(acc.w * w, sc.w, sh.w);
    *(float4*)(HE + (size_t)e * DD + c4) = o;
}

// ---------------- e2v (CSR gather) ----------------
__global__ __launch_bounds__(128) void k_e2v(const float* __restrict__ HE,
                                             float* __restrict__ Xout) {
    int v  = blockIdx.x;
    int c4 = threadIdx.x * 4;
    int s = g_off_v[v], t = g_off_v[v + 1];
    float4 acc = make_float4(0.f, 0.f, 0.f, 0.f);
    int j = s;
    for (; j + 4 <= t; j += 4) {
        int e0 = g_csr_v_e[j + 0];
        int e1 = g_csr_v_e[j + 1];
        int e2 = g_csr_v_e[j + 2];
        int e3 = g_csr_v_e[j + 3];
        float4 h0 = *(const float4*)(HE + (size_t)e0 * DD + c4);
        float4 h1 = *(const float4*)(HE + (size_t)e1 * DD + c4);
        float4 h2 = *(const float4*)(HE + (size_t)e2 * DD + c4);
        float4 h3 = *(const float4*)(HE + (size_t)e3 * DD + c4);
        acc.x += (h0.x + h1.x) + (h2.x + h3.x);
        acc.y += (h0.y + h1.y) + (h2.y + h3.y);
        acc.z += (h0.z + h1.z) + (h2.z + h3.z);
        acc.w += (h0.w + h1.w) + (h2.w + h3.w);
    }
    for (; j < t; j++) {
        int e = g_csr_v_e[j];
        float4 h = *(const float4*)(HE + (size_t)e * DD + c4);
        acc.x += h.x; acc.y += h.y; acc.z += h.z; acc.w += h.w;
    }
    float w = 1.0f / (float)max(t - s, 1);
    float4 o = make_float4(acc.x * w, acc.y * w, acc.z * w, acc.w * w);
    *(float4*)(Xout + (size_t)v * DD + c4) = o;
}

// ---------------- launcher ----------------
extern "C" void kernel_launch(void* const* d_in, const int* in_sizes, int n_in,
                              void* d_out, int out_size) {
    const float* X     = (const float*)d_in[0];
    const float* W     = (const float*)d_in[1];
    const float* b     = (const float*)d_in[2];
    const float* gamma = (const float*)d_in[3];
    const float* beta  = (const float*)d_in[4];
    const int* v_idx   = (const int*)d_in[5];
    const int* e_idx   = (const int*)d_in[6];

    float* Xout = (float*)d_out;
    float* HE   = Xout + (size_t)NV * DD;

    k_zero_misc<<<(NV + 255) / 256, 256>>>();
    long expected = (long)(NV + NE) * DD;
    if ((long)out_size > expected)
        k_zero<<<64, 256>>>(Xout + expected, (long)out_size - expected);

    // CSR build
    k_deg<<<(NM + 255) / 256, 256>>>(v_idx, e_idx);
    k_scan<<<1, 1024>>>(0);
    k_scan<<<1, 1024>>>(1);
    k_fill<<<(NM + 255) / 256, 256>>>(v_idx, e_idx);

    // split inputs to bf16 hi/lo
    k_splitX<<<2048, 256>>>(X);
    k_splitW<<<(DD * DD + 255) / 256, 256>>>(W);

    // tensor-core (mma.sync) GEMM  Y = X @ W + b
    dim3 gg(DD / 128, (NV + 127) / 128);
    k_gemm_mma<<<gg, 256>>>(b);

    // BN stats folded into per-column scale/shift
    k_colstats<<<256, DD>>>();
    k_finalize<<<1, DD>>>(gamma, beta);

    // gather-based segment means
    k_v2e<<<NE, 128>>>(HE);
    k_e2v<<<NV, 128>>>(HE, Xout);
}

// round 6
// speedup vs baseline: 3.2394x; 1.2711x over previous
#include <cuda_runtime.h>
#include <cuda_bf16.h>
#include <cstdint>

#define NV 50000
#define NE 10000
#define NM 200000
#define DD 512
#define BN_EPS 1e-5f

// ---------------- scratch (static device globals; no allocation) ----------------
__device__ float g_Y[(size_t)NV * DD];            // GEMM output (pre-BN)
__device__ __nv_bfloat16 g_Xh[(size_t)NV * DD];   // hi bf16 split of X
__device__ __nv_bfloat16 g_Xl[(size_t)NV * DD];   // lo bf16 split of X
__device__ __nv_bfloat16 g_Wth[DD * DD];          // W^T hi split  [n][k]
__device__ __nv_bfloat16 g_Wtl[DD * DD];          // W^T lo split  [n][k]
__device__ float g_stats[2 * DD];
__device__ float g_scale[DD];
__device__ float g_shift[DD];
__device__ int   g_deg_e[NE];
__device__ int   g_deg_v[NV];
__device__ int   g_cur_e[NE];
__device__ int   g_cur_v[NV];
__device__ int   g_off_e[NE + 1];
__device__ int   g_off_v[NV + 1];
__device__ int   g_csr_e_v[NM];
__device__ int   g_csr_v_e[NM];
__device__ int   g_bsum[64];

// ---------------- helpers ----------------
__device__ __forceinline__ uint32_t smem_u32(const void* p) {
    uint32_t a;
    asm("{ .reg .u64 t; cvta.to.shared.u64 t, %1; cvt.u32.u64 %0, t; }" : "=r"(a) : "l"(p));
    return a;
}
__device__ __forceinline__ void ldm_x4(uint32_t* r, uint32_t addr) {
    asm volatile("ldmatrix.sync.aligned.m8n8.x4.shared.b16 {%0,%1,%2,%3}, [%4];"
                 : "=r"(r[0]), "=r"(r[1]), "=r"(r[2]), "=r"(r[3]) : "r"(addr));
}
__device__ __forceinline__ void mma16816(float* d, const uint32_t* a, const uint32_t* b) {
    asm volatile(
        "mma.sync.aligned.m16n8k16.row.col.f32.bf16.bf16.f32 "
        "{%0,%1,%2,%3}, {%4,%5,%6,%7}, {%8,%9}, {%0,%1,%2,%3};"
        : "+f"(d[0]), "+f"(d[1]), "+f"(d[2]), "+f"(d[3])
        : "r"(a[0]), "r"(a[1]), "r"(a[2]), "r"(a[3]), "r"(b[0]), "r"(b[1]));
}
__device__ __forceinline__ void cp16(uint32_t saddr, const void* g, bool pred) {
    int sz = pred ? 16 : 0;
    asm volatile("cp.async.cg.shared.global [%0], [%1], 16, %2;"
                 :: "r"(saddr), "l"(g), "r"(sz) : "memory");
}
__device__ __forceinline__ void cp_commit() {
    asm volatile("cp.async.commit_group;" ::: "memory");
}
template <int N>
__device__ __forceinline__ void cp_wait() {
    asm volatile("cp.async.wait_group %0;" :: "n"(N) : "memory");
}

// ---------------- zeroing ----------------
__global__ void k_zero(float* p, long n) {
    long stride = (long)gridDim.x * blockDim.x;
    for (long i = (long)blockIdx.x * blockDim.x + threadIdx.x; i < n; i += stride)
        p[i] = 0.0f;
}
__global__ void k_zero_misc() {
    int i = blockIdx.x * blockDim.x + threadIdx.x;
    if (i < 2 * DD) g_stats[i] = 0.0f;
    if (i < NE) { g_deg_e[i] = 0; g_cur_e[i] = 0; }
    if (i < NV) { g_deg_v[i] = 0; g_cur_v[i] = 0; }
}

// ---------------- degree counting ----------------
__global__ void k_deg(const int* __restrict__ v_idx, const int* __restrict__ e_idx) {
    int i = blockIdx.x * blockDim.x + threadIdx.x;
    if (i < NM) {
        atomicAdd(&g_deg_v[v_idx[i]], 1);
        atomicAdd(&g_deg_e[e_idx[i]], 1);
    }
}

// ---------------- multi-block exclusive scan ----------------
#define SCHUNK 2048
__global__ void k_scan_part(int mode) {
    const int* __restrict__ deg = (mode == 0) ? g_deg_e : g_deg_v;
    const int n = (mode == 0) ? NE : NV;
    int b = blockIdx.x;
    int start = b * SCHUNK;
    int end = min(start + SCHUNK, n);
    int s = 0;
    for (int i = start + threadIdx.x; i < end; i += 256) s += deg[i];
#pragma unroll
    for (int d = 16; d; d >>= 1) s += __shfl_down_sync(0xFFFFFFFFu, s, d);
    __shared__ int ws[8];
    if ((threadIdx.x & 31) == 0) ws[threadIdx.x >> 5] = s;
    __syncthreads();
    if (threadIdx.x == 0) {
        int t = 0;
#pragma unroll
        for (int w = 0; w < 8; w++) t += ws[w];
        g_bsum[b] = t;
    }
}
__global__ void k_scan_mid(int nb) {
    if (threadIdx.x == 0) {
        int run = 0;
        for (int i = 0; i < nb; i++) { int t = g_bsum[i]; g_bsum[i] = run; run += t; }
        g_bsum[nb] = run;
    }
}
__global__ void k_scan_final(int mode) {
    const int* __restrict__ deg = (mode == 0) ? g_deg_e : g_deg_v;
    int* __restrict__ off       = (mode == 0) ? g_off_e : g_off_v;
    const int n = (mode == 0) ? NE : NV;
    const int tid  = threadIdx.x;
    const int lane = tid & 31;
    const int w    = tid >> 5;
    int start = blockIdx.x * SCHUNK;
    int carry = g_bsum[blockIdx.x];
    __shared__ int ws[8];
    __shared__ int btotal;
    for (int batch = 0; batch < SCHUNK / 256; batch++) {
        int i = start + batch * 256 + tid;
        int v = (i < n) ? deg[i] : 0;
        int s = v;
#pragma unroll
        for (int d = 1; d < 32; d <<= 1) {
            int t = __shfl_up_sync(0xFFFFFFFFu, s, d);
            if (lane >= d) s += t;
        }
        if (lane == 31) ws[w] = s;
        __syncthreads();
        if (tid == 0) {
            int run = 0;
#pragma unroll
            for (int j = 0; j < 8; j++) { int t = ws[j]; ws[j] = run; run += t; }
            btotal = run;
        }
        __syncthreads();
        s += ws[w];
        if (i < n) off[i] = carry + s - v;
        if (i == n - 1) off[n] = carry + s;
        carry += btotal;
        __syncthreads();
    }
}

// ---------------- CSR fill ----------------
__global__ void k_fill(const int* __restrict__ v_idx, const int* __restrict__ e_idx) {
    int i = blockIdx.x * blockDim.x + threadIdx.x;
    if (i < NM) {
        int v = v_idx[i];
        int e = e_idx[i];
        int pe = atomicAdd(&g_cur_e[e], 1);
        g_csr_e_v[g_off_e[e] + pe] = v;
        int pv = atomicAdd(&g_cur_v[v], 1);
        g_csr_v_e[g_off_v[v] + pv] = e;
    }
}

// ---------------- split X into bf16 hi/lo ----------------
__global__ void k_splitX(const float* __restrict__ X) {
    long n4 = (long)NV * DD / 4;
    long stride = (long)gridDim.x * blockDim.x;
    for (long i4 = (long)blockIdx.x * blockDim.x + threadIdx.x; i4 < n4; i4 += stride) {
        float4 v = ((const float4*)X)[i4];
        __nv_bfloat16 h0 = __float2bfloat16(v.x);
        __nv_bfloat16 h1 = __float2bfloat16(v.y);
        __nv_bfloat16 h2 = __float2bfloat16(v.z);
        __nv_bfloat16 h3 = __float2bfloat16(v.w);
        __nv_bfloat16 l0 = __float2bfloat16(v.x - __bfloat162float(h0));
        __nv_bfloat16 l1 = __float2bfloat16(v.y - __bfloat162float(h1));
        __nv_bfloat16 l2 = __float2bfloat16(v.z - __bfloat162float(h2));
        __nv_bfloat16 l3 = __float2bfloat16(v.w - __bfloat162float(h3));
        __nv_bfloat162 hh01; hh01.x = h0; hh01.y = h1;
        __nv_bfloat162 hh23; hh23.x = h2; hh23.y = h3;
        __nv_bfloat162 ll01; ll01.x = l0; ll01.y = l1;
        __nv_bfloat162 ll23; ll23.x = l2; ll23.y = l3;
        ((__nv_bfloat162*)g_Xh)[i4 * 2 + 0] = hh01;
        ((__nv_bfloat162*)g_Xh)[i4 * 2 + 1] = hh23;
        ((__nv_bfloat162*)g_Xl)[i4 * 2 + 0] = ll01;
        ((__nv_bfloat162*)g_Xl)[i4 * 2 + 1] = ll23;
    }
}

// ---------------- split + transpose W ----------------
__global__ void k_splitW(const float* __restrict__ W) {
    int i = blockIdx.x * blockDim.x + threadIdx.x;  // i = n*512 + k
    if (i < DD * DD) {
        int n = i >> 9, k = i & 511;
        float v = W[(size_t)k * DD + n];
        __nv_bfloat16 h = __float2bfloat16(v);
        __nv_bfloat16 l = __float2bfloat16(v - __bfloat162float(h));
        g_Wth[i] = h;
        g_Wtl[i] = l;
    }
}

// ---------------- mma.sync GEMM with cp.async double buffering ----------------
#define SPAD 40
#define BUFB (128 * SPAD * 2)   // bytes per buffer
__global__ __launch_bounds__(256, 2) void k_gemm_mma(const float* __restrict__ bias) {
    __shared__ __align__(16) __nv_bfloat16 As[2][128 * SPAD];
    __shared__ __align__(16) __nv_bfloat16 Bs[2][128 * SPAD];

    const int tid    = threadIdx.x;
    const int wid    = tid >> 5;
    const int lane   = tid & 31;
    const int warp_m = wid >> 2;   // 0..1
    const int warp_n = wid & 3;    // 0..3
    const int row0   = blockIdx.y * 128;
    const int n0     = blockIdx.x * 128;

    const uint32_t as_base = smem_u32(As);
    const uint32_t bs_base = smem_u32(Bs);

    // per-thread cp.async coordinates: 2 x uint4 per tile per array
    const int ld_r0 = tid >> 2;               // 0..63
    const int ld_q  = (tid & 3) * 8;          // bf16 col within 32

    const int a_row = warp_m * 64 + (lane & 15);
    const int a_col = ((lane >> 4) << 3);
    const int b_row = warp_n * 32 + ((lane >> 4) << 3) + (lane & 7);
    const int b_col = ((lane >> 3) & 1) << 3;

    float acc[4][4][4];
#pragma unroll
    for (int i = 0; i < 4; i++)
#pragma unroll
        for (int j = 0; j < 4; j++)
#pragma unroll
            for (int r = 0; r < 4; r++) acc[i][j][r] = 0.0f;

    // flattened k loop: 48 tiles = 3 segs x 16 BK-tiles of 32
    auto issue_tile = [&](int kg, int buf) {
        const int seg = kg >> 4;
        const int k0  = (kg & 15) * 32;
        const __nv_bfloat16* Ap = (seg < 2) ? g_Xh : g_Xl;
        const __nv_bfloat16* Bp = (seg == 1) ? g_Wtl : g_Wth;
#pragma unroll
        for (int i = 0; i < 2; i++) {
            int r = ld_r0 + i * 64;
            int gr = row0 + r;
            bool ok = gr < NV;
            int grc = ok ? gr : 0;
            cp16(as_base + buf * BUFB + (r * SPAD + ld_q) * 2,
                 Ap + (size_t)grc * DD + k0 + ld_q, ok);
            cp16(bs_base + buf * BUFB + (r * SPAD + ld_q) * 2,
                 Bp + (size_t)(n0 + r) * DD + k0 + ld_q, true);
        }
        cp_commit();
    };

    issue_tile(0, 0);
#pragma unroll 1
    for (int kg = 0; kg < 48; kg++) {
        const int buf = kg & 1;
        if (kg + 1 < 48) {
            issue_tile(kg + 1, buf ^ 1);
            cp_wait<1>();
        } else {
            cp_wait<0>();
        }
        __syncthreads();

        const uint32_t ab = as_base + buf * BUFB;
        const uint32_t bb = bs_base + buf * BUFB;
#pragma unroll
        for (int k16 = 0; k16 < 2; k16++) {
            const int kk = k16 * 16;
            uint32_t a[4][4];
#pragma unroll
            for (int mt = 0; mt < 4; mt++)
                ldm_x4(a[mt], ab + ((a_row + mt * 16) * SPAD + a_col + kk) * 2);
            uint32_t bfr[2][4];
#pragma unroll
            for (int np = 0; np < 2; np++)
                ldm_x4(bfr[np], bb + ((b_row + np * 16) * SPAD + b_col + kk) * 2);
#pragma unroll
            for (int mt = 0; mt < 4; mt++)
#pragma unroll
                for (int nt = 0; nt < 4; nt++)
                    mma16816(acc[mt][nt], a[mt], &bfr[nt >> 1][(nt & 1) * 2]);
        }
        __syncthreads();
    }

    // epilogue: D frag -> g_Y (+bias)
    const int mrow = lane >> 2;
    const int mcol = (lane & 3) * 2;
#pragma unroll
    for (int mt = 0; mt < 4; mt++) {
#pragma unroll
        for (int nt = 0; nt < 4; nt++) {
            int gc = n0 + warp_n * 32 + nt * 8 + mcol;
            float2 bb2 = *(const float2*)(bias + gc);
            int gr0 = row0 + warp_m * 64 + mt * 16 + mrow;
            if (gr0 < NV) {
                float2 o = make_float2(acc[mt][nt][0] + bb2.x, acc[mt][nt][1] + bb2.y);
                *(float2*)(g_Y + (size_t)gr0 * DD + gc) = o;
            }
            int gr1 = gr0 + 8;
            if (gr1 < NV) {
                float2 o = make_float2(acc[mt][nt][2] + bb2.x, acc[mt][nt][3] + bb2.y);
                *(float2*)(g_Y + (size_t)gr1 * DD + gc) = o;
            }
        }
    }
}

// ---------------- per-column BN stats over g_Y ----------------
__global__ void k_colstats() {
    int c = threadIdx.x;
    float s = 0.0f, s2 = 0.0f;
    for (int r = blockIdx.x; r < NV; r += gridDim.x) {
        float v = g_Y[(size_t)r * DD + c];
        s += v;
        s2 += v * v;
    }
    atomicAdd(&g_stats[c], s);
    atomicAdd(&g_stats[DD + c], s2);
}

__global__ void k_finalize(const float* __restrict__ gamma, const float* __restrict__ beta) {
    int c = threadIdx.x;
    float mu  = g_stats[c] * (1.0f / NV);
    float var = g_stats[DD + c] * (1.0f / NV) - mu * mu;
    float rs  = rsqrtf(var + BN_EPS);
    float sc  = gamma[c] * rs;
    g_scale[c] = sc;
    g_shift[c] = beta[c] - mu * sc;
}

// ---------------- v2e (CSR gather) ----------------
__global__ __launch_bounds__(128) void k_v2e(float* __restrict__ HE) {
    int e  = blockIdx.x;
    int c4 = threadIdx.x * 4;
    int s = g_off_e[e], t = g_off_e[e + 1];
    float4 acc = make_float4(0.f, 0.f, 0.f, 0.f);
    int j = s;
    for (; j + 4 <= t; j += 4) {
        int v0 = g_csr_e_v[j + 0];
        int v1 = g_csr_e_v[j + 1];
        int v2 = g_csr_e_v[j + 2];
        int v3 = g_csr_e_v[j + 3];
        float4 y0 = *(const float4*)(g_Y + (size_t)v0 * DD + c4);
        float4 y1 = *(const float4*)(g_Y + (size_t)v1 * DD + c4);
        float4 y2 = *(const float4*)(g_Y + (size_t)v2 * DD + c4);
        float4 y3 = *(const float4*)(g_Y + (size_t)v3 * DD + c4);
        acc.x += (y0.x + y1.x) + (y2.x + y3.x);
        acc.y += (y0.y + y1.y) + (y2.y + y3.y);
        acc.z += (y0.z + y1.z) + (y2.z + y3.z);
        acc.w += (y0.w + y1.w) + (y2.w + y3.w);
    }
    for (; j < t; j++) {
        int v = g_csr_e_v[j];
        float4 y = *(const float4*)(g_Y + (size_t)v * DD + c4);
        acc.x += y.x; acc.y += y.y; acc.z += y.z; acc.w += y.w;
    }
    float w = 1.0f / (float)max(t - s, 1);
    float4 sc = *(const float4*)(g_scale + c4);
    float4 sh = *(const float4*)(g_shift + c4);
    float4 o;
    o.x = fmaf(acc.x * w, sc.x, sh.x);
    o.y = fmaf(acc.y * w, sc.y, sh.y);
    o.z = fmaf(acc.z * w, sc.z, sh.z);
    o.w = fmaf(acc.w * w, sc.w, sh.w);
    *(float4*)(HE + (size_t)e * DD + c4) = o;
}

// ---------------- e2v (CSR gather) ----------------
__global__ __launch_bounds__(128) void k_e2v(const float* __restrict__ HE,
                                             float* __restrict__ Xout) {
    int v  = blockIdx.x;
    int c4 = threadIdx.x * 4;
    int s = g_off_v[v], t = g_off_v[v + 1];
    float4 acc = make_float4(0.f, 0.f, 0.f, 0.f);
    int j = s;
    for (; j + 4 <= t; j += 4) {
        int e0 = g_csr_v_e[j + 0];
        int e1 = g_csr_v_e[j + 1];
        int e2 = g_csr_v_e[j + 2];
        int e3 = g_csr_v_e[j + 3];
        float4 h0 = *(const float4*)(HE + (size_t)e0 * DD + c4);
        float4 h1 = *(const float4*)(HE + (size_t)e1 * DD + c4);
        float4 h2 = *(const float4*)(HE + (size_t)e2 * DD + c4);
        float4 h3 = *(const float4*)(HE + (size_t)e3 * DD + c4);
        acc.x += (h0.x + h1.x) + (h2.x + h3.x);
        acc.y += (h0.y + h1.y) + (h2.y + h3.y);
        acc.z += (h0.z + h1.z) + (h2.z + h3.z);
        acc.w += (h0.w + h1.w) + (h2.w + h3.w);
    }
    for (; j < t; j++) {
        int e = g_csr_v_e[j];
        float4 h = *(const float4*)(HE + (size_t)e * DD + c4);
        acc.x += h.x; acc.y += h.y; acc.z += h.z; acc.w += h.w;
    }
    float w = 1.0f / (float)max(t - s, 1);
    float4 o = make_float4(acc.x * w, acc.y * w, acc.z * w, acc.w * w);
    *(float4*)(Xout + (size_t)v * DD + c4) = o;
}

// ---------------- launcher ----------------
extern "C" void kernel_launch(void* const* d_in, const int* in_sizes, int n_in,
                              void* d_out, int out_size) {
    const float* X     = (const float*)d_in[0];
    const float* W     = (const float*)d_in[1];
    const float* b     = (const float*)d_in[2];
    const float* gamma = (const float*)d_in[3];
    const float* beta  = (const float*)d_in[4];
    const int* v_idx   = (const int*)d_in[5];
    const int* e_idx   = (const int*)d_in[6];

    float* Xout = (float*)d_out;
    float* HE   = Xout + (size_t)NV * DD;

    k_zero_misc<<<(NV + 255) / 256, 256>>>();
    long expected = (long)(NV + NE) * DD;
    if ((long)out_size > expected)
        k_zero<<<64, 256>>>(Xout + expected, (long)out_size - expected);

    // CSR build
    k_deg<<<(NM + 255) / 256, 256>>>(v_idx, e_idx);
    int nb_e = (NE + SCHUNK - 1) / SCHUNK;
    int nb_v = (NV + SCHUNK - 1) / SCHUNK;
    k_scan_part<<<nb_e, 256>>>(0);
    k_scan_mid<<<1, 32>>>(nb_e);
    k_scan_final<<<nb_e, 256>>>(0);
    k_scan_part<<<nb_v, 256>>>(1);
    k_scan_mid<<<1, 32>>>(nb_v);
    k_scan_final<<<nb_v, 256>>>(1);
    k_fill<<<(NM + 255) / 256, 256>>>(v_idx, e_idx);

    // split inputs to bf16 hi/lo
    k_splitX<<<2048, 256>>>(X);
    k_splitW<<<(DD * DD + 255) / 256, 256>>>(W);

    // tensor-core (mma.sync) GEMM  Y = X @ W + b
    dim3 gg(DD / 128, (NV + 127) / 128);
    k_gemm_mma<<<gg, 256>>>(b);

    // BN stats folded into per-column scale/shift
    k_colstats<<<512, DD>>>();
    k_finalize<<<1, DD>>>(gamma, beta);

    // gather-based segment means
    k_v2e<<<NE, 128>>>(HE);
    k_e2v<<<NV, 128>>>(HE, Xout);
}